// round 7
// baseline (speedup 1.0000x reference)
#include <cuda_runtime.h>
#include <cuda_fp16.h>
#include <math.h>

// ===========================================================================
// Fused IFS generator on mma.sync (HMMA), v2: fp32-resident LN epilogues.
// 1 CTA = 64 rows, 256 threads (8 warps: 2M x 4N, warp tile 32x128).
// Whole 512-col layer accumulated in registers (128 fp32/thread) -> LN applied
// in fp32, no fp16 pre-LN stash. A fp16 smem in-place; WT fp16 pre-transposed
// in global, streamed via double-buffered cp.async (64-K slices, full N).
// ===========================================================================

#define THREADS 256
#define EPSV    1e-5f
#define THRESH  0.9f

#define A_STRIDE_B  1040                 // 520 halves (≡4 words mod 32: no conflicts)
#define WS_STRIDE_B 144                  // 72 halves  (≡4 words mod 32)
#define A_OFF       0                    // 64 * 1040 = 66560
#define WS_OFF      66560
#define WS_BUF      73728                // 512 rows * 144 B
#define RED_OFF     (WS_OFF + 2 * WS_BUF)     // 214016: sSum[64], sSq[64]
#define BOUT_OFF    (RED_OFF + 512)           // 214528
#define SMEM_BYTES  (BOUT_OFF + 256)          // 214784

// pre-transposed fp16 weights WT[n][k] = W[k][n]
__device__ __align__(16) __half g_Wt1[512 * 256];
__device__ __align__(16) __half g_Wta[512 * 512];
__device__ __align__(16) __half g_Wtb[512 * 512];
__device__ __align__(16) __half g_Wto[64 * 512];     // rows 35..63 zero
__device__ __align__(16) __half g_h[(size_t)131072 * 512];   // residual stash

// ---------------- asm helpers (sm_80-baseline legal) ----------------
__device__ __forceinline__ unsigned smem_u32(const void* p) {
    unsigned a;
    asm("{ .reg .u64 t; cvta.to.shared.u64 t, %1; cvt.u32.u64 %0, t; }"
        : "=r"(a) : "l"(p));
    return a;
}

#define LDMX4(r0, r1, r2, r3, addr) \
    asm volatile("ldmatrix.sync.aligned.m8n8.x4.shared.b16 {%0,%1,%2,%3}, [%4];" \
                 : "=r"(r0), "=r"(r1), "=r"(r2), "=r"(r3) : "r"(addr))

#define MMA16816(c, a, b) \
    asm volatile("mma.sync.aligned.m16n8k16.row.col.f32.f16.f16.f32 " \
                 "{%0,%1,%2,%3},{%4,%5,%6,%7},{%8,%9},{%0,%1,%2,%3};" \
                 : "+f"((c)[0]), "+f"((c)[1]), "+f"((c)[2]), "+f"((c)[3]) \
                 : "r"((a)[0]), "r"((a)[1]), "r"((a)[2]), "r"((a)[3]), \
                   "r"((b)[0]), "r"((b)[1]))

#define CP_ASYNC16(dst, src) \
    asm volatile("cp.async.ca.shared.global [%0], [%1], 16;" :: "r"(dst), "l"(src))
#define CP_COMMIT() asm volatile("cp.async.commit_group;")
#define CP_WAIT1()  asm volatile("cp.async.wait_group 1;")
#define CP_WAIT0()  asm volatile("cp.async.wait_group 0;")

#define STS32(addr, v) \
    asm volatile("st.shared.b32 [%0], %1;" :: "r"(addr), "r"(v))
#define STS64(addr, v0, v1) \
    asm volatile("st.shared.v2.b32 [%0], {%1,%2};" :: "r"(addr), "r"(v0), "r"(v1))
#define LDS128(v0, v1, v2, v3, addr) \
    asm volatile("ld.shared.v4.b32 {%0,%1,%2,%3}, [%4];" \
                 : "=r"(v0), "=r"(v1), "=r"(v2), "=r"(v3) : "r"(addr))
#define STS128(addr, v0, v1, v2, v3) \
    asm volatile("st.shared.v4.b32 [%0], {%1,%2,%3,%4};" \
                 :: "r"(addr), "r"(v0), "r"(v1), "r"(v2), "r"(v3))

// ---------------------------------------------------------------------------
// stage one [NROWS][64-k] fp16 slice of WT (row stride Kdim halves) -> smem
template <int NROWS>
__device__ __forceinline__ void stage(const __half* __restrict__ WTg, int Kdim,
                                      int ks, unsigned dstBase, int tid)
{
#pragma unroll
    for (int c = tid; c < NROWS * 8; c += THREADS) {
        int row = c >> 3, seg = c & 7;
        const char* src = (const char*)(WTg + (size_t)row * Kdim + ks * 64) + seg * 16;
        CP_ASYNC16(dstBase + (unsigned)(row * WS_STRIDE_B + seg * 16), src);
    }
    CP_COMMIT();
}

// ---------------------------------------------------------------------------
// full-N GEMM: acc[2][NT][4] = A[64][Kdim] @ WT[NROWS][Kdim]^T
template <int NT, int NROWS>
__device__ __forceinline__ void gemm_full(const __half* __restrict__ WTg, int Kdim,
                                          unsigned sbA, unsigned sbW,
                                          float (&acc)[2][NT][4],
                                          int tid, int lane, int mi, int ni)
{
#pragma unroll
    for (int mt = 0; mt < 2; mt++)
#pragma unroll
        for (int nt = 0; nt < NT; nt++)
#pragma unroll
            for (int q = 0; q < 4; q++) acc[mt][nt][q] = 0.f;

    const unsigned aRS = (((unsigned)lane >> 3) & 1u) * 8u + ((unsigned)lane & 7u);
    const unsigned aCS = ((unsigned)lane >> 4) << 4;
    const unsigned bRS = (((unsigned)lane >> 4) << 3) + ((unsigned)lane & 7u);
    const unsigned bCS = (((unsigned)lane >> 3) & 1u) << 4;
    const unsigned aBase = sbA + (unsigned)(mi * 32 + aRS) * A_STRIDE_B + aCS;
    const unsigned bOff  = (unsigned)(ni * NT * 8 + bRS) * WS_STRIDE_B + bCS;

    const int S = Kdim >> 6;
    stage<NROWS>(WTg, Kdim, 0, sbW, tid);
    for (int ks = 0; ks < S; ks++) {
        const unsigned cur = sbW + (unsigned)(ks & 1) * WS_BUF;
        if (ks + 1 < S) {
            stage<NROWS>(WTg, Kdim, ks + 1, sbW + (unsigned)((ks + 1) & 1) * WS_BUF, tid);
            CP_WAIT1();
        } else {
            CP_WAIT0();
        }
        __syncthreads();
#pragma unroll
        for (int ki = 0; ki < 4; ki++) {
            const unsigned kb = (unsigned)(ks * 64 + ki * 16) * 2u;
            unsigned a[2][4];
#pragma unroll
            for (int mt = 0; mt < 2; mt++)
                LDMX4(a[mt][0], a[mt][1], a[mt][2], a[mt][3],
                      aBase + (unsigned)(mt * 16) * A_STRIDE_B + kb);
            unsigned b[NT][2];
#pragma unroll
            for (int p = 0; p < NT / 2; p++) {
                unsigned r0, r1, r2, r3;
                LDMX4(r0, r1, r2, r3,
                      cur + bOff + (unsigned)(p * 16) * WS_STRIDE_B + (unsigned)(ki * 32));
                b[2 * p][0] = r0; b[2 * p][1] = r1;
                b[2 * p + 1][0] = r2; b[2 * p + 1][1] = r3;
            }
#pragma unroll
            for (int mt = 0; mt < 2; mt++)
#pragma unroll
                for (int nt = 0; nt < NT; nt++)
                    MMA16816(acc[mt][nt], a[mt], b[nt]);
        }
        __syncthreads();
    }
}

// ---------------------------------------------------------------------------
// LN epilogue fully in fp32 from resident acc. ACT: 0 none, 1 relu, 2 silu.
template <int ACT>
__device__ __forceinline__ void ln_epilogue(float (&acc)[2][16][4],
                                            const float* __restrict__ bias,
                                            const float* __restrict__ gamma,
                                            const float* __restrict__ beta,
                                            unsigned sbA, float* sSum, float* sSq,
                                            int lane, int mi, int ni)
{
    const int qp = lane & 3, g = lane >> 2;
    float srow[4] = {0.f, 0.f, 0.f, 0.f};
    float ssqr[4] = {0.f, 0.f, 0.f, 0.f};

#pragma unroll
    for (int mt = 0; mt < 2; mt++)
#pragma unroll
        for (int nt = 0; nt < 16; nt++)
#pragma unroll
            for (int rh = 0; rh < 2; rh++) {
                const int c0 = ni * 128 + nt * 8 + qp * 2;
                float x0 = acc[mt][nt][rh * 2]     + __ldg(bias + c0);
                float x1 = acc[mt][nt][rh * 2 + 1] + __ldg(bias + c0 + 1);
                acc[mt][nt][rh * 2] = x0; acc[mt][nt][rh * 2 + 1] = x1;
                const int s = mt * 2 + rh;
                srow[s] += x0 + x1;
                ssqr[s] += x0 * x0 + x1 * x1;
            }
#pragma unroll
    for (int s = 0; s < 4; s++) {
        srow[s] += __shfl_xor_sync(0xffffffffu, srow[s], 1);
        srow[s] += __shfl_xor_sync(0xffffffffu, srow[s], 2);
        ssqr[s] += __shfl_xor_sync(0xffffffffu, ssqr[s], 1);
        ssqr[s] += __shfl_xor_sync(0xffffffffu, ssqr[s], 2);
    }
    if (qp == 0) {
#pragma unroll
        for (int s = 0; s < 4; s++) {
            const int row = mi * 32 + (s >> 1) * 16 + (s & 1) * 8 + g;
            atomicAdd(&sSum[row], srow[s]);
            atomicAdd(&sSq[row],  ssqr[s]);
        }
    }
    __syncthreads();

    float mu[4], rs[4];
#pragma unroll
    for (int s = 0; s < 4; s++) {
        const int row = mi * 32 + (s >> 1) * 16 + (s & 1) * 8 + g;
        float m = sSum[row] * (1.f / 512.f);
        float v = fmaxf(sSq[row] * (1.f / 512.f) - m * m, 0.f);
        mu[s] = m; rs[s] = rsqrtf(v + EPSV);
    }
#pragma unroll
    for (int mt = 0; mt < 2; mt++)
#pragma unroll
        for (int nt = 0; nt < 16; nt++)
#pragma unroll
            for (int rh = 0; rh < 2; rh++) {
                const int s = mt * 2 + rh;
                const int c0 = ni * 128 + nt * 8 + qp * 2;
                float n0 = (acc[mt][nt][rh * 2]     - mu[s]) * rs[s] * __ldg(gamma + c0)     + __ldg(beta + c0);
                float n1 = (acc[mt][nt][rh * 2 + 1] - mu[s]) * rs[s] * __ldg(gamma + c0 + 1) + __ldg(beta + c0 + 1);
                if (ACT == 1) { n0 = fmaxf(n0, 0.f); n1 = fmaxf(n1, 0.f); }
                else if (ACT == 2) {
                    n0 = n0 / (1.f + __expf(-n0));
                    n1 = n1 / (1.f + __expf(-n1));
                }
                __half2 hp = __floats2half2_rn(n0, n1);
                const int row = mi * 32 + mt * 16 + rh * 8 + g;
                STS32(sbA + (unsigned)(row * A_STRIDE_B + c0 * 2), *(unsigned*)&hp);
            }
    __syncthreads();
}

// ---------------------------------------------------------------------------
__global__ void __launch_bounds__(THREADS, 1)
ifs_main(const float* __restrict__ z,
         const float* __restrict__ b1, const float* __restrict__ g1,
         const float* __restrict__ be1,
         const float* __restrict__ ba, const float* __restrict__ ga,
         const float* __restrict__ bea,
         const float* __restrict__ bb, const float* __restrict__ gb,
         const float* __restrict__ beb,
         const float* __restrict__ bout,
         float* __restrict__ out, int Btot)
{
    extern __shared__ char smc[];
    const unsigned sb  = smem_u32(smc);
    const unsigned sbW = sb + WS_OFF;
    const int tid = threadIdx.x, lane = tid & 31, wid = tid >> 5;
    const int mi = wid & 1, ni = wid >> 1;
    const int row0 = blockIdx.x * 64;

    float* sSum = (float*)(smc + RED_OFF);
    float* sSq  = sSum + 64;
    float* sBo  = (float*)(smc + BOUT_OFF);
    if (tid < 35) sBo[tid] = bout[tid];

    // z -> A (fp16)
    for (int i = tid; i < 64 * 64; i += THREADS) {
        int r = i >> 6, c4 = i & 63;
        float4 zv = *(const float4*)&z[(size_t)(row0 + r) * 256 + c4 * 4];
        __half2 h0 = __floats2half2_rn(zv.x, zv.y);
        __half2 h1 = __floats2half2_rn(zv.z, zv.w);
        STS64(sb + (unsigned)(r * A_STRIDE_B + c4 * 8),
              *(unsigned*)&h0, *(unsigned*)&h1);
    }
    if (tid < 64) { sSum[tid] = 0.f; sSq[tid] = 0.f; }
    __syncthreads();

    {
        float acc[2][16][4];
        gemm_full<16, 512>(g_Wt1, 256, sb, sbW, acc, tid, lane, mi, ni);
        ln_epilogue<1>(acc, b1, g1, be1, sb, sSum, sSq, lane, mi, ni);
    }

    // stash h (A) -> global, coalesced
    for (int c = tid; c < 64 * 64; c += THREADS) {
        int r = c >> 6, seg = c & 63;
        unsigned v0, v1, v2, v3;
        LDS128(v0, v1, v2, v3, sb + (unsigned)(r * A_STRIDE_B + seg * 16));
        uint4 vv = {v0, v1, v2, v3};
        *(uint4*)((char*)g_h + ((size_t)(row0 + r) * 512 + seg * 8) * 2) = vv;
    }
    if (tid < 64) { sSum[tid] = 0.f; sSq[tid] = 0.f; }
    __syncthreads();

    {
        float acc[2][16][4];
        gemm_full<16, 512>(g_Wta, 512, sb, sbW, acc, tid, lane, mi, ni);
        ln_epilogue<2>(acc, ba, ga, bea, sb, sSum, sSq, lane, mi, ni);
    }
    if (tid < 64) { sSum[tid] = 0.f; sSq[tid] = 0.f; }
    __syncthreads();
    {
        float acc[2][16][4];
        gemm_full<16, 512>(g_Wtb, 512, sb, sbW, acc, tid, lane, mi, ni);
        ln_epilogue<0>(acc, bb, gb, beb, sb, sSum, sSq, lane, mi, ni);
    }

    // h2 = yb + h (fp32 add, single rounding)
    for (int c = tid; c < 64 * 64; c += THREADS) {
        int r = c >> 6, seg = c & 63;
        const unsigned aaddr = sb + (unsigned)(r * A_STRIDE_B + seg * 16);
        uint4 hv = *(const uint4*)((const char*)g_h +
                                   ((size_t)(row0 + r) * 512 + seg * 8) * 2);
        unsigned v0, v1, v2, v3;
        LDS128(v0, v1, v2, v3, aaddr);
        float2 a0 = __half22float2(*(__half2*)&v0), h0 = __half22float2(*(__half2*)&hv.x);
        float2 a1 = __half22float2(*(__half2*)&v1), h1 = __half22float2(*(__half2*)&hv.y);
        float2 a2 = __half22float2(*(__half2*)&v2), h2 = __half22float2(*(__half2*)&hv.z);
        float2 a3 = __half22float2(*(__half2*)&v3), h3 = __half22float2(*(__half2*)&hv.w);
        __half2 o0 = __floats2half2_rn(a0.x + h0.x, a0.y + h0.y);
        __half2 o1 = __floats2half2_rn(a1.x + h1.x, a1.y + h1.y);
        __half2 o2 = __floats2half2_rn(a2.x + h2.x, a2.y + h2.y);
        __half2 o3 = __floats2half2_rn(a3.x + h3.x, a3.y + h3.y);
        STS128(aaddr, *(unsigned*)&o0, *(unsigned*)&o1,
                      *(unsigned*)&o2, *(unsigned*)&o3);
    }
    __syncthreads();

    // ---- tail: x = h2 @ Wout + bout, SVD clamp + softmax ----
    {
        float acc[2][2][4];
        gemm_full<2, 64>(g_Wto, 512, sb, sbW, acc, tid, lane, mi, ni);

        float* sX = (float*)(smc + WS_OFF);     // [64][65] fp32, staging now free
        const int qp = lane & 3, g = lane >> 2;
#pragma unroll
        for (int mt = 0; mt < 2; mt++)
#pragma unroll
            for (int nt = 0; nt < 2; nt++)
#pragma unroll
                for (int rh = 0; rh < 2; rh++) {
                    const int row = mi * 32 + mt * 16 + rh * 8 + g;
                    const int col = ni * 16 + nt * 8 + qp * 2;
                    sX[row * 65 + col]     = acc[mt][nt][rh * 2];
                    sX[row * 65 + col + 1] = acc[mt][nt][rh * 2 + 1];
                }
        __syncthreads();

        if (tid < 64) {
            const int r = tid;
            float x[35];
#pragma unroll
            for (int j = 0; j < 35; j++) x[j] = sX[r * 65 + j] + sBo[j];

            const size_t gr = (size_t)(row0 + r);
            float* op = out + gr * 30;
#pragma unroll
            for (int t = 0; t < 5; t++) {
                float a = x[t * 6], b = x[t * 6 + 1], tx = x[t * 6 + 2];
                float c = x[t * 6 + 3], d = x[t * 6 + 4], ty = x[t * 6 + 5];
                float E = 0.5f * (a + d), F = 0.5f * (a - d);
                float G = 0.5f * (c + b), H = 0.5f * (c - b);
                float Q = sqrtf(E * E + H * H);
                float R = sqrtf(F * F + G * G);
                float s1 = Q + R, s2v = Q - R;
                float s1c = fminf(s1, THRESH);
                float s2c = fminf(fmaxf(s2v, -THRESH), THRESH);
                float Qc = 0.5f * (s1c + s2c), Rc = 0.5f * (s1c - s2c);
                float rQ = Qc / fmaxf(Q, 1e-30f);
                float rR = Rc / fmaxf(R, 1e-30f);
                op[t * 6 + 0] =  rQ * E + rR * F;
                op[t * 6 + 1] = -rQ * H + rR * G;
                op[t * 6 + 2] = tx;
                op[t * 6 + 3] =  rQ * H + rR * G;
                op[t * 6 + 4] =  rQ * E - rR * F;
                op[t * 6 + 5] = ty;
            }
            float mx = x[30];
#pragma unroll
            for (int k = 1; k < 5; k++) mx = fmaxf(mx, x[30 + k]);
            float e[5], ssum = 0.f;
#pragma unroll
            for (int k = 0; k < 5; k++) { e[k] = __expf(x[30 + k] - mx); ssum += e[k]; }
            float inv = 1.f / ssum;
            float* pp = out + (size_t)Btot * 30 + gr * 5;
#pragma unroll
            for (int k = 0; k < 5; k++) pp[k] = e[k] * inv;
        }
    }
}

// ---------------------------------------------------------------------------
// single merged prep: all four WT[n][k] = fp16(W[k][n]) transposes.
__global__ void prep_all(const float* __restrict__ W1, const float* __restrict__ Wa,
                         const float* __restrict__ Wb, const float* __restrict__ Wout)
{
    int id = blockIdx.x * blockDim.x + threadIdx.x;
    if (id < 131072) {                       // W1: [256][512] -> WT1[512][256]
        int n = id >> 8, k = id & 255;
        g_Wt1[id] = __float2half_rn(W1[(size_t)k * 512 + n]);
    } else if (id < 393216) {                // Wa
        int t = id - 131072, n = t >> 9, k = t & 511;
        g_Wta[t] = __float2half_rn(Wa[(size_t)k * 512 + n]);
    } else if (id < 655360) {                // Wb
        int t = id - 393216, n = t >> 9, k = t & 511;
        g_Wtb[t] = __float2half_rn(Wb[(size_t)k * 512 + n]);
    } else if (id < 688128) {                // Wout: [512][35] -> WTo[64][512]
        int t = id - 655360, n = t >> 9, k = t & 511;
        g_Wto[t] = (n < 35) ? __float2half_rn(Wout[(size_t)k * 35 + n])
                            : __float2half_rn(0.f);
    }
}

// ---------------------------------------------------------------------------
extern "C" void kernel_launch(void* const* d_in, const int* in_sizes, int n_in,
                              void* d_out, int out_size)
{
    const float* z    = (const float*)d_in[0];
    const float* W1   = (const float*)d_in[1];
    const float* b1   = (const float*)d_in[2];
    const float* g1   = (const float*)d_in[3];
    const float* be1  = (const float*)d_in[4];
    const float* Wa   = (const float*)d_in[5];
    const float* ba   = (const float*)d_in[6];
    const float* ga   = (const float*)d_in[7];
    const float* bea  = (const float*)d_in[8];
    const float* Wb   = (const float*)d_in[9];
    const float* bb   = (const float*)d_in[10];
    const float* gb   = (const float*)d_in[11];
    const float* beb  = (const float*)d_in[12];
    const float* Wout = (const float*)d_in[13];
    const float* bout = (const float*)d_in[14];
    float* out = (float*)d_out;

    const int Btot = in_sizes[0] / 256;

    prep_all<<<(688128 + 255) / 256, 256>>>(W1, Wa, Wb, Wout);

    cudaFuncSetAttribute(ifs_main,
                         cudaFuncAttributeMaxDynamicSharedMemorySize, SMEM_BYTES);
    ifs_main<<<Btot / 64, THREADS, SMEM_BYTES>>>(
        z, b1, g1, be1, ba, ga, bea, bb, gb, beb, bout, out, Btot);
}

// round 11
// speedup vs baseline: 1.0871x; 1.0871x over previous
#include <cuda_runtime.h>
#include <cuda_fp16.h>
#include <math.h>

// ===========================================================================
// Fused IFS generator on mma.sync (HMMA), v3: 512 threads, fp32-resident LN.
// 1 CTA = 64 rows, 512 threads (16 warps: 2M x 8N, warp tile 32x64, NT=8).
// acc = 64 fp32/thread -> no spills; 16 warps/SM for latency hiding.
// A fp16 smem in-place; WT fp16 pre-transposed in global, double-buffered
// cp.async.cg staging (64-K slices, full N).
// ===========================================================================

#define THREADS 512
#define EPSV    1e-5f
#define THRESH  0.9f

#define A_STRIDE_B  1040                 // 520 halves (≡4 words mod 32: conflict-free)
#define WS_STRIDE_B 144                  // 72 halves  (≡4 words mod 32)
#define WS_OFF      66560                // A = 64*1040
#define WS_BUF      73728                // 512 rows * 144 B
#define RED_OFF     (WS_OFF + 2 * WS_BUF)     // 214016: sSum[64], sSq[64]
#define BOUT_OFF    (RED_OFF + 512)           // 214528
#define SMEM_BYTES  (BOUT_OFF + 256)          // 214784

// pre-transposed fp16 weights WT[n][k] = W[k][n]
__device__ __align__(16) __half g_Wt1[512 * 256];
__device__ __align__(16) __half g_Wta[512 * 512];
__device__ __align__(16) __half g_Wtb[512 * 512];
__device__ __align__(16) __half g_Wto[128 * 512];    // rows 35..127 zero
__device__ __align__(16) __half g_h[(size_t)131072 * 512];   // residual stash

// ---------------- asm helpers (sm_80-baseline legal) ----------------
__device__ __forceinline__ unsigned smem_u32(const void* p) {
    unsigned a;
    asm("{ .reg .u64 t; cvta.to.shared.u64 t, %1; cvt.u32.u64 %0, t; }"
        : "=r"(a) : "l"(p));
    return a;
}

#define LDMX4(r0, r1, r2, r3, addr) \
    asm volatile("ldmatrix.sync.aligned.m8n8.x4.shared.b16 {%0,%1,%2,%3}, [%4];" \
                 : "=r"(r0), "=r"(r1), "=r"(r2), "=r"(r3) : "r"(addr))

#define MMA16816(c, a, b) \
    asm volatile("mma.sync.aligned.m16n8k16.row.col.f32.f16.f16.f32 " \
                 "{%0,%1,%2,%3},{%4,%5,%6,%7},{%8,%9},{%0,%1,%2,%3};" \
                 : "+f"((c)[0]), "+f"((c)[1]), "+f"((c)[2]), "+f"((c)[3]) \
                 : "r"((a)[0]), "r"((a)[1]), "r"((a)[2]), "r"((a)[3]), \
                   "r"((b)[0]), "r"((b)[1]))

#define CP_ASYNC16(dst, src) \
    asm volatile("cp.async.cg.shared.global [%0], [%1], 16;" :: "r"(dst), "l"(src))
#define CP_COMMIT() asm volatile("cp.async.commit_group;")
#define CP_WAIT1()  asm volatile("cp.async.wait_group 1;")
#define CP_WAIT0()  asm volatile("cp.async.wait_group 0;")

#define STS32(addr, v) \
    asm volatile("st.shared.b32 [%0], %1;" :: "r"(addr), "r"(v))
#define STS64(addr, v0, v1) \
    asm volatile("st.shared.v2.b32 [%0], {%1,%2};" :: "r"(addr), "r"(v0), "r"(v1))
#define LDS128(v0, v1, v2, v3, addr) \
    asm volatile("ld.shared.v4.b32 {%0,%1,%2,%3}, [%4];" \
                 : "=r"(v0), "=r"(v1), "=r"(v2), "=r"(v3) : "r"(addr))
#define STS128(addr, v0, v1, v2, v3) \
    asm volatile("st.shared.v4.b32 [%0], {%1,%2,%3,%4};" \
                 :: "r"(addr), "r"(v0), "r"(v1), "r"(v2), "r"(v3))

// ---------------------------------------------------------------------------
// stage one [NROWS][64-k] fp16 slice of WT (row stride Kdim halves) -> smem
template <int NROWS>
__device__ __forceinline__ void stage(const __half* __restrict__ WTg, int Kdim,
                                      int ks, unsigned dstBase, int tid)
{
#pragma unroll
    for (int c = tid; c < NROWS * 8; c += THREADS) {
        int row = c >> 3, seg = c & 7;
        const char* src = (const char*)(WTg + (size_t)row * Kdim + ks * 64) + seg * 16;
        CP_ASYNC16(dstBase + (unsigned)(row * WS_STRIDE_B + seg * 16), src);
    }
    CP_COMMIT();
}

// ---------------------------------------------------------------------------
// full-N GEMM: acc[2][NT][4] = A[64][Kdim] @ WT[NROWS][Kdim]^T
template <int NT, int NROWS>
__device__ __forceinline__ void gemm_full(const __half* __restrict__ WTg, int Kdim,
                                          unsigned sbA, unsigned sbW,
                                          float (&acc)[2][NT][4],
                                          int tid, int lane, int mi, int ni)
{
#pragma unroll
    for (int mt = 0; mt < 2; mt++)
#pragma unroll
        for (int nt = 0; nt < NT; nt++)
#pragma unroll
            for (int q = 0; q < 4; q++) acc[mt][nt][q] = 0.f;

    const unsigned aRS = (((unsigned)lane >> 3) & 1u) * 8u + ((unsigned)lane & 7u);
    const unsigned aCS = ((unsigned)lane >> 4) << 4;
    const unsigned bRS = (((unsigned)lane >> 4) << 3) + ((unsigned)lane & 7u);
    const unsigned bCS = (((unsigned)lane >> 3) & 1u) << 4;
    const unsigned aBase = sbA + (unsigned)(mi * 32 + aRS) * A_STRIDE_B + aCS;
    const unsigned bOff  = (unsigned)(ni * NT * 8 + bRS) * WS_STRIDE_B + bCS;

    const int S = Kdim >> 6;
    stage<NROWS>(WTg, Kdim, 0, sbW, tid);
    for (int ks = 0; ks < S; ks++) {
        const unsigned cur = sbW + (unsigned)(ks & 1) * WS_BUF;
        if (ks + 1 < S) {
            stage<NROWS>(WTg, Kdim, ks + 1, sbW + (unsigned)((ks + 1) & 1) * WS_BUF, tid);
            CP_WAIT1();
        } else {
            CP_WAIT0();
        }
        __syncthreads();
#pragma unroll
        for (int ki = 0; ki < 4; ki++) {
            const unsigned kb = (unsigned)(ks * 64 + ki * 16) * 2u;
            unsigned a[2][4];
#pragma unroll
            for (int mt = 0; mt < 2; mt++)
                LDMX4(a[mt][0], a[mt][1], a[mt][2], a[mt][3],
                      aBase + (unsigned)(mt * 16) * A_STRIDE_B + kb);
            unsigned b[NT][2];
#pragma unroll
            for (int p = 0; p < NT / 2; p++) {
                unsigned r0, r1, r2, r3;
                LDMX4(r0, r1, r2, r3,
                      cur + bOff + (unsigned)(p * 16) * WS_STRIDE_B + (unsigned)(ki * 32));
                b[2 * p][0] = r0; b[2 * p][1] = r1;
                b[2 * p + 1][0] = r2; b[2 * p + 1][1] = r3;
            }
#pragma unroll
            for (int mt = 0; mt < 2; mt++)
#pragma unroll
                for (int nt = 0; nt < NT; nt++)
                    MMA16816(acc[mt][nt], a[mt], b[nt]);
        }
        __syncthreads();
    }
}

// ---------------------------------------------------------------------------
// LN epilogue fully in fp32 from resident acc. ACT: 0 none, 1 relu, 2 silu.
// Warp owns cols [ni*64, ni*64+64). Cross-warp row stats via shared atomics.
template <int ACT>
__device__ __forceinline__ void ln_epilogue(float (&acc)[2][8][4],
                                            const float* __restrict__ bias,
                                            const float* __restrict__ gamma,
                                            const float* __restrict__ beta,
                                            unsigned sbA, float* sSum, float* sSq,
                                            int lane, int mi, int ni)
{
    const int qp = lane & 3, g = lane >> 2;
    float srow[4] = {0.f, 0.f, 0.f, 0.f};
    float ssqr[4] = {0.f, 0.f, 0.f, 0.f};

#pragma unroll
    for (int mt = 0; mt < 2; mt++)
#pragma unroll
        for (int nt = 0; nt < 8; nt++)
#pragma unroll
            for (int rh = 0; rh < 2; rh++) {
                const int c0 = ni * 64 + nt * 8 + qp * 2;
                float x0 = acc[mt][nt][rh * 2]     + __ldg(bias + c0);
                float x1 = acc[mt][nt][rh * 2 + 1] + __ldg(bias + c0 + 1);
                acc[mt][nt][rh * 2] = x0; acc[mt][nt][rh * 2 + 1] = x1;
                const int s = mt * 2 + rh;
                srow[s] += x0 + x1;
                ssqr[s] += x0 * x0 + x1 * x1;
            }
#pragma unroll
    for (int s = 0; s < 4; s++) {
        srow[s] += __shfl_xor_sync(0xffffffffu, srow[s], 1);
        srow[s] += __shfl_xor_sync(0xffffffffu, srow[s], 2);
        ssqr[s] += __shfl_xor_sync(0xffffffffu, ssqr[s], 1);
        ssqr[s] += __shfl_xor_sync(0xffffffffu, ssqr[s], 2);
    }
    if (qp == 0) {
#pragma unroll
        for (int s = 0; s < 4; s++) {
            const int row = mi * 32 + (s >> 1) * 16 + (s & 1) * 8 + g;
            atomicAdd(&sSum[row], srow[s]);
            atomicAdd(&sSq[row],  ssqr[s]);
        }
    }
    __syncthreads();

    float mu[4], rs[4];
#pragma unroll
    for (int s = 0; s < 4; s++) {
        const int row = mi * 32 + (s >> 1) * 16 + (s & 1) * 8 + g;
        float m = sSum[row] * (1.f / 512.f);
        float v = fmaxf(sSq[row] * (1.f / 512.f) - m * m, 0.f);
        mu[s] = m; rs[s] = rsqrtf(v + EPSV);
    }
#pragma unroll
    for (int mt = 0; mt < 2; mt++)
#pragma unroll
        for (int nt = 0; nt < 8; nt++)
#pragma unroll
            for (int rh = 0; rh < 2; rh++) {
                const int s = mt * 2 + rh;
                const int c0 = ni * 64 + nt * 8 + qp * 2;
                float n0 = (acc[mt][nt][rh * 2]     - mu[s]) * rs[s] * __ldg(gamma + c0)     + __ldg(beta + c0);
                float n1 = (acc[mt][nt][rh * 2 + 1] - mu[s]) * rs[s] * __ldg(gamma + c0 + 1) + __ldg(beta + c0 + 1);
                if (ACT == 1) { n0 = fmaxf(n0, 0.f); n1 = fmaxf(n1, 0.f); }
                else if (ACT == 2) {
                    n0 = n0 / (1.f + __expf(-n0));
                    n1 = n1 / (1.f + __expf(-n1));
                }
                __half2 hp = __floats2half2_rn(n0, n1);
                const int row = mi * 32 + mt * 16 + rh * 8 + g;
                STS32(sbA + (unsigned)(row * A_STRIDE_B + c0 * 2), *(unsigned*)&hp);
            }
    __syncthreads();
}

// ---------------------------------------------------------------------------
__global__ void __launch_bounds__(THREADS, 1)
ifs_main(const float* __restrict__ z,
         const float* __restrict__ b1, const float* __restrict__ g1,
         const float* __restrict__ be1,
         const float* __restrict__ ba, const float* __restrict__ ga,
         const float* __restrict__ bea,
         const float* __restrict__ bb, const float* __restrict__ gb,
         const float* __restrict__ beb,
         const float* __restrict__ bout,
         float* __restrict__ out, int Btot)
{
    extern __shared__ char smc[];
    const unsigned sb  = smem_u32(smc);
    const unsigned sbW = sb + WS_OFF;
    const int tid = threadIdx.x, lane = tid & 31, wid = tid >> 5;
    const int mi = wid & 1, ni = wid >> 1;            // 2M x 8N
    const int row0 = blockIdx.x * 64;

    float* sSum = (float*)(smc + RED_OFF);
    float* sSq  = sSum + 64;
    float* sBo  = (float*)(smc + BOUT_OFF);
    if (tid < 35) sBo[tid] = bout[tid];

    // z -> A (fp16)
    for (int i = tid; i < 64 * 64; i += THREADS) {
        int r = i >> 6, c4 = i & 63;
        float4 zv = *(const float4*)&z[(size_t)(row0 + r) * 256 + c4 * 4];
        __half2 h0 = __floats2half2_rn(zv.x, zv.y);
        __half2 h1 = __floats2half2_rn(zv.z, zv.w);
        STS64(sb + (unsigned)(r * A_STRIDE_B + c4 * 8),
              *(unsigned*)&h0, *(unsigned*)&h1);
    }
    if (tid < 64) { sSum[tid] = 0.f; sSq[tid] = 0.f; }
    __syncthreads();

    {
        float acc[2][8][4];
        gemm_full<8, 512>(g_Wt1, 256, sb, sbW, acc, tid, lane, mi, ni);
        ln_epilogue<1>(acc, b1, g1, be1, sb, sSum, sSq, lane, mi, ni);
    }

    // stash h (A) -> global, coalesced
    for (int c = tid; c < 64 * 64; c += THREADS) {
        int r = c >> 6, seg = c & 63;
        unsigned v0, v1, v2, v3;
        LDS128(v0, v1, v2, v3, sb + (unsigned)(r * A_STRIDE_B + seg * 16));
        uint4 vv = {v0, v1, v2, v3};
        *(uint4*)((char*)g_h + ((size_t)(row0 + r) * 512 + seg * 8) * 2) = vv;
    }
    if (tid < 64) { sSum[tid] = 0.f; sSq[tid] = 0.f; }
    __syncthreads();

    {
        float acc[2][8][4];
        gemm_full<8, 512>(g_Wta, 512, sb, sbW, acc, tid, lane, mi, ni);
        ln_epilogue<2>(acc, ba, ga, bea, sb, sSum, sSq, lane, mi, ni);
    }
    if (tid < 64) { sSum[tid] = 0.f; sSq[tid] = 0.f; }
    __syncthreads();
    {
        float acc[2][8][4];
        gemm_full<8, 512>(g_Wtb, 512, sb, sbW, acc, tid, lane, mi, ni);
        ln_epilogue<0>(acc, bb, gb, beb, sb, sSum, sSq, lane, mi, ni);
    }

    // h2 = yb + h (fp32 add, single rounding)
    for (int c = tid; c < 64 * 64; c += THREADS) {
        int r = c >> 6, seg = c & 63;
        const unsigned aaddr = sb + (unsigned)(r * A_STRIDE_B + seg * 16);
        uint4 hv = *(const uint4*)((const char*)g_h +
                                   ((size_t)(row0 + r) * 512 + seg * 8) * 2);
        unsigned v0, v1, v2, v3;
        LDS128(v0, v1, v2, v3, aaddr);
        float2 a0 = __half22float2(*(__half2*)&v0), h0 = __half22float2(*(__half2*)&hv.x);
        float2 a1 = __half22float2(*(__half2*)&v1), h1 = __half22float2(*(__half2*)&hv.y);
        float2 a2 = __half22float2(*(__half2*)&v2), h2 = __half22float2(*(__half2*)&hv.z);
        float2 a3 = __half22float2(*(__half2*)&v3), h3 = __half22float2(*(__half2*)&hv.w);
        __half2 o0 = __floats2half2_rn(a0.x + h0.x, a0.y + h0.y);
        __half2 o1 = __floats2half2_rn(a1.x + h1.x, a1.y + h1.y);
        __half2 o2 = __floats2half2_rn(a2.x + h2.x, a2.y + h2.y);
        __half2 o3 = __floats2half2_rn(a3.x + h3.x, a3.y + h3.y);
        STS128(aaddr, *(unsigned*)&o0, *(unsigned*)&o1,
                      *(unsigned*)&o2, *(unsigned*)&o3);
    }
    __syncthreads();

    // ---- tail: x = h2 @ Wout(+pad) + bout, SVD clamp + softmax ----
    {
        float acc[2][2][4];
        gemm_full<2, 128>(g_Wto, 512, sb, sbW, acc, tid, lane, mi, ni);

        float* sX = (float*)(smc + WS_OFF);     // [64][65] fp32, staging now free
        const int qp = lane & 3, g = lane >> 2;
#pragma unroll
        for (int mt = 0; mt < 2; mt++)
#pragma unroll
            for (int nt = 0; nt < 2; nt++)
                if (ni * 16 + nt * 8 < 64) {
#pragma unroll
                    for (int rh = 0; rh < 2; rh++) {
                        const int row = mi * 32 + mt * 16 + rh * 8 + g;
                        const int col = ni * 16 + nt * 8 + qp * 2;
                        sX[row * 65 + col]     = acc[mt][nt][rh * 2];
                        sX[row * 65 + col + 1] = acc[mt][nt][rh * 2 + 1];
                    }
                }
        __syncthreads();

        if (tid < 64) {
            const int r = tid;
            float x[35];
#pragma unroll
            for (int j = 0; j < 35; j++) x[j] = sX[r * 65 + j] + sBo[j];

            const size_t gr = (size_t)(row0 + r);
            float* op = out + gr * 30;
#pragma unroll
            for (int t = 0; t < 5; t++) {
                float a = x[t * 6], b = x[t * 6 + 1], tx = x[t * 6 + 2];
                float c = x[t * 6 + 3], d = x[t * 6 + 4], ty = x[t * 6 + 5];
                float E = 0.5f * (a + d), F = 0.5f * (a - d);
                float G = 0.5f * (c + b), H = 0.5f * (c - b);
                float Q = sqrtf(E * E + H * H);
                float R = sqrtf(F * F + G * G);
                float s1 = Q + R, s2v = Q - R;
                float s1c = fminf(s1, THRESH);
                float s2c = fminf(fmaxf(s2v, -THRESH), THRESH);
                float Qc = 0.5f * (s1c + s2c), Rc = 0.5f * (s1c - s2c);
                float rQ = Qc / fmaxf(Q, 1e-30f);
                float rR = Rc / fmaxf(R, 1e-30f);
                op[t * 6 + 0] =  rQ * E + rR * F;
                op[t * 6 + 1] = -rQ * H + rR * G;
                op[t * 6 + 2] = tx;
                op[t * 6 + 3] =  rQ * H + rR * G;
                op[t * 6 + 4] =  rQ * E - rR * F;
                op[t * 6 + 5] = ty;
            }
            float mx = x[30];
#pragma unroll
            for (int k = 1; k < 5; k++) mx = fmaxf(mx, x[30 + k]);
            float e[5], ssum = 0.f;
#pragma unroll
            for (int k = 0; k < 5; k++) { e[k] = __expf(x[30 + k] - mx); ssum += e[k]; }
            float inv = 1.f / ssum;
            float* pp = out + (size_t)Btot * 30 + gr * 5;
#pragma unroll
            for (int k = 0; k < 5; k++) pp[k] = e[k] * inv;
        }
    }
}

// ---------------------------------------------------------------------------
// single merged prep: all four WT[n][k] = fp16(W[k][n]) transposes.
__global__ void prep_all(const float* __restrict__ W1, const float* __restrict__ Wa,
                         const float* __restrict__ Wb, const float* __restrict__ Wout)
{
    int id = blockIdx.x * blockDim.x + threadIdx.x;
    if (id < 131072) {                       // W1: [256][512] -> WT1[512][256]
        int n = id >> 8, k = id & 255;
        g_Wt1[id] = __float2half_rn(W1[(size_t)k * 512 + n]);
    } else if (id < 393216) {                // Wa
        int t = id - 131072, n = t >> 9, k = t & 511;
        g_Wta[t] = __float2half_rn(Wa[(size_t)k * 512 + n]);
    } else if (id < 655360) {                // Wb
        int t = id - 393216, n = t >> 9, k = t & 511;
        g_Wtb[t] = __float2half_rn(Wb[(size_t)k * 512 + n]);
    } else if (id < 720896) {                // Wout: [512][35] -> WTo[128][512]
        int t = id - 655360, n = t >> 9, k = t & 511;
        g_Wto[t] = (n < 35) ? __float2half_rn(Wout[(size_t)k * 35 + n])
                            : __float2half_rn(0.f);
    }
}

// ---------------------------------------------------------------------------
extern "C" void kernel_launch(void* const* d_in, const int* in_sizes, int n_in,
                              void* d_out, int out_size)
{
    const float* z    = (const float*)d_in[0];
    const float* W1   = (const float*)d_in[1];
    const float* b1   = (const float*)d_in[2];
    const float* g1   = (const float*)d_in[3];
    const float* be1  = (const float*)d_in[4];
    const float* Wa   = (const float*)d_in[5];
    const float* ba   = (const float*)d_in[6];
    const float* ga   = (const float*)d_in[7];
    const float* bea  = (const float*)d_in[8];
    const float* Wb   = (const float*)d_in[9];
    const float* bb   = (const float*)d_in[10];
    const float* gb   = (const float*)d_in[11];
    const float* beb  = (const float*)d_in[12];
    const float* Wout = (const float*)d_in[13];
    const float* bout = (const float*)d_in[14];
    float* out = (float*)d_out;

    const int Btot = in_sizes[0] / 256;

    prep_all<<<(720896 + 255) / 256, 256>>>(W1, Wa, Wb, Wout);

    cudaFuncSetAttribute(ifs_main,
                         cudaFuncAttributeMaxDynamicSharedMemorySize, SMEM_BYTES);
    ifs_main<<<Btot / 64, THREADS, SMEM_BYTES>>>(
        z, b1, g1, be1, ba, ga, bea, bb, gb, beb, bout, out, Btot);
}

// round 13
// speedup vs baseline: 1.2547x; 1.1541x over previous
#include <cuda_runtime.h>
#include <cuda_fp16.h>
#include <math.h>

// ===========================================================================
// Fused IFS generator on mma.sync (HMMA), v4.
// 1 CTA = 64 rows, 512 threads (16 warps: 2M x 8N, warp tile 32x64, NT=8).
// v4 vs v3: single __syncthreads per k-slice (stage-after-sync), LN params
// staged to smem per epilogue (no per-element __ldg), tail GEMM NT=1 (64-row
// padded Wout, x4 ldmatrix serves 2 ki of B).
// ===========================================================================

#define THREADS 512
#define EPSV    1e-5f
#define THRESH  0.9f

#define A_STRIDE_B  1040                 // 520 halves (≡4 words mod 32: conflict-free)
#define WS_STRIDE_B 144                  // 72 halves  (≡4 words mod 32)
#define WS_OFF      66560                // A = 64*1040
#define WS_BUF      73728                // 512 rows * 144 B
#define RED_OFF     (WS_OFF + 2 * WS_BUF)     // 214016: sSum[64], sSq[64]
#define BOUT_OFF    (RED_OFF + 512)           // 214528
#define SMEM_BYTES  (BOUT_OFF + 256)          // 214784

// pre-transposed fp16 weights WT[n][k] = W[k][n]
__device__ __align__(16) __half g_Wt1[512 * 256];
__device__ __align__(16) __half g_Wta[512 * 512];
__device__ __align__(16) __half g_Wtb[512 * 512];
__device__ __align__(16) __half g_Wto[64 * 512];     // rows 35..63 zero
__device__ __align__(16) __half g_h[(size_t)131072 * 512];   // residual stash

// ---------------- asm helpers (sm_80-baseline legal) ----------------
__device__ __forceinline__ unsigned smem_u32(const void* p) {
    unsigned a;
    asm("{ .reg .u64 t; cvta.to.shared.u64 t, %1; cvt.u32.u64 %0, t; }"
        : "=r"(a) : "l"(p));
    return a;
}

#define LDMX4(r0, r1, r2, r3, addr) \
    asm volatile("ldmatrix.sync.aligned.m8n8.x4.shared.b16 {%0,%1,%2,%3}, [%4];" \
                 : "=r"(r0), "=r"(r1), "=r"(r2), "=r"(r3) : "r"(addr))

#define MMA16816(c, a, b) \
    asm volatile("mma.sync.aligned.m16n8k16.row.col.f32.f16.f16.f32 " \
                 "{%0,%1,%2,%3},{%4,%5,%6,%7},{%8,%9},{%0,%1,%2,%3};" \
                 : "+f"((c)[0]), "+f"((c)[1]), "+f"((c)[2]), "+f"((c)[3]) \
                 : "r"((a)[0]), "r"((a)[1]), "r"((a)[2]), "r"((a)[3]), \
                   "r"((b)[0]), "r"((b)[1]))

#define CP_ASYNC16(dst, src) \
    asm volatile("cp.async.cg.shared.global [%0], [%1], 16;" :: "r"(dst), "l"(src))
#define CP_COMMIT() asm volatile("cp.async.commit_group;")
#define CP_WAIT0()  asm volatile("cp.async.wait_group 0;")

#define STS32(addr, v) \
    asm volatile("st.shared.b32 [%0], %1;" :: "r"(addr), "r"(v))
#define STS64(addr, v0, v1) \
    asm volatile("st.shared.v2.b32 [%0], {%1,%2};" :: "r"(addr), "r"(v0), "r"(v1))
#define LDS128(v0, v1, v2, v3, addr) \
    asm volatile("ld.shared.v4.b32 {%0,%1,%2,%3}, [%4];" \
                 : "=r"(v0), "=r"(v1), "=r"(v2), "=r"(v3) : "r"(addr))
#define STS128(addr, v0, v1, v2, v3) \
    asm volatile("st.shared.v4.b32 [%0], {%1,%2,%3,%4};" \
                 :: "r"(addr), "r"(v0), "r"(v1), "r"(v2), "r"(v3))

// ---------------------------------------------------------------------------
// stage one [NROWS][64-k] fp16 slice of WT (row stride Kdim halves) -> smem
template <int NROWS>
__device__ __forceinline__ void stage(const __half* __restrict__ WTg, int Kdim,
                                      int ks, unsigned dstBase, int tid)
{
#pragma unroll
    for (int c = tid; c < NROWS * 8; c += THREADS) {
        int row = c >> 3, seg = c & 7;
        const char* src = (const char*)(WTg + (size_t)row * Kdim + ks * 64) + seg * 16;
        CP_ASYNC16(dstBase + (unsigned)(row * WS_STRIDE_B + seg * 16), src);
    }
    CP_COMMIT();
}

// ---------------------------------------------------------------------------
// full-N GEMM: acc[2][NT][4] = A[64][Kdim] @ WT[NROWS][Kdim]^T
// ONE __syncthreads per slice: wait -> sync -> stage next -> compute.
// NOTE: no trailing sync; caller must sync before touching A or staging smem.
template <int NT, int NROWS>
__device__ __forceinline__ void gemm_full(const __half* __restrict__ WTg, int Kdim,
                                          unsigned sbA, unsigned sbW,
                                          float (&acc)[2][NT][4],
                                          int tid, int lane, int mi, int ni)
{
#pragma unroll
    for (int mt = 0; mt < 2; mt++)
#pragma unroll
        for (int nt = 0; nt < NT; nt++)
#pragma unroll
            for (int q = 0; q < 4; q++) acc[mt][nt][q] = 0.f;

    const unsigned aRS = (((unsigned)lane >> 3) & 1u) * 8u + ((unsigned)lane & 7u);
    const unsigned aCS = ((unsigned)lane >> 4) << 4;
    const unsigned bRS = (((unsigned)lane >> 4) << 3) + ((unsigned)lane & 7u);
    const unsigned bCS = (((unsigned)lane >> 3) & 1u) << 4;
    const unsigned aBase = sbA + (unsigned)(mi * 32 + aRS) * A_STRIDE_B + aCS;
    const unsigned bOff  = (unsigned)(ni * NT * 8 + bRS) * WS_STRIDE_B + bCS;

    const int S = Kdim >> 6;
    stage<NROWS>(WTg, Kdim, 0, sbW, tid);
    for (int ks = 0; ks < S; ks++) {
        const unsigned cur = sbW + (unsigned)(ks & 1) * WS_BUF;
        CP_WAIT0();                       // data for slice ks arrived
        __syncthreads();                  // visible to all; buf(ks+1) free
        if (ks + 1 < S)
            stage<NROWS>(WTg, Kdim, ks + 1,
                         sbW + (unsigned)((ks + 1) & 1) * WS_BUF, tid);
#pragma unroll
        for (int ki = 0; ki < 4; ki++) {
            const unsigned kb = (unsigned)(ks * 64 + ki * 16) * 2u;
            unsigned a[2][4];
#pragma unroll
            for (int mt = 0; mt < 2; mt++)
                LDMX4(a[mt][0], a[mt][1], a[mt][2], a[mt][3],
                      aBase + (unsigned)(mt * 16) * A_STRIDE_B + kb);
            unsigned b[NT][2];
#pragma unroll
            for (int p = 0; p < NT / 2; p++) {
                unsigned r0, r1, r2, r3;
                LDMX4(r0, r1, r2, r3,
                      cur + bOff + (unsigned)(p * 16) * WS_STRIDE_B + (unsigned)(ki * 32));
                b[2 * p][0] = r0; b[2 * p][1] = r1;
                b[2 * p + 1][0] = r2; b[2 * p + 1][1] = r3;
            }
#pragma unroll
            for (int mt = 0; mt < 2; mt++)
#pragma unroll
                for (int nt = 0; nt < NT; nt++)
                    MMA16816(acc[mt][nt], a[mt], b[nt]);
        }
    }
}

// ---------------------------------------------------------------------------
// tail GEMM: NT=1 over 64 padded N rows. x4 ldmatrix covers two ki of B.
__device__ __forceinline__ void gemm_tail(const __half* __restrict__ WTg,
                                          unsigned sbA, unsigned sbW,
                                          float (&acc)[2][4],
                                          int tid, int lane, int mi, int ni)
{
#pragma unroll
    for (int mt = 0; mt < 2; mt++)
#pragma unroll
        for (int q = 0; q < 4; q++) acc[mt][q] = 0.f;

    const unsigned aRS = (((unsigned)lane >> 3) & 1u) * 8u + ((unsigned)lane & 7u);
    const unsigned aCS = ((unsigned)lane >> 4) << 4;
    const unsigned aBase = sbA + (unsigned)(mi * 32 + aRS) * A_STRIDE_B + aCS;
    // B: row n = ni*8 + (lane&7); 4 matrices at col bytes +0/+16/+32/+48
    const unsigned bOff = (unsigned)(ni * 8 + ((unsigned)lane & 7u)) * WS_STRIDE_B
                        + (((unsigned)lane >> 3) << 4);

    const int S = 8;                      // K = 512
    stage<64>(WTg, 512, 0, sbW, tid);
    for (int ks = 0; ks < S; ks++) {
        const unsigned cur = sbW + (unsigned)(ks & 1) * WS_BUF;
        CP_WAIT0();
        __syncthreads();
        if (ks + 1 < S)
            stage<64>(WTg, 512, ks + 1, sbW + (unsigned)((ks + 1) & 1) * WS_BUF, tid);
        unsigned bq0, bq1, bq2, bq3;
#pragma unroll
        for (int ki = 0; ki < 4; ki++) {
            const unsigned kb = (unsigned)(ks * 64 + ki * 16) * 2u;
            unsigned a[2][4];
#pragma unroll
            for (int mt = 0; mt < 2; mt++)
                LDMX4(a[mt][0], a[mt][1], a[mt][2], a[mt][3],
                      aBase + (unsigned)(mt * 16) * A_STRIDE_B + kb);
            if ((ki & 1) == 0)
                LDMX4(bq0, bq1, bq2, bq3, cur + bOff + (unsigned)(ki * 32));
            unsigned bb[2];
            bb[0] = (ki & 1) ? bq2 : bq0;
            bb[1] = (ki & 1) ? bq3 : bq1;
#pragma unroll
            for (int mt = 0; mt < 2; mt++)
                MMA16816(acc[mt], a[mt], bb);
        }
    }
}

// ---------------------------------------------------------------------------
// LN epilogue fully in fp32 from resident acc. ACT: 0 none, 1 relu, 2 silu.
// Params staged into smem (idle staging region buf0). Ends with syncthreads.
template <int ACT>
__device__ __forceinline__ void ln_epilogue(float (&acc)[2][8][4],
                                            const float* __restrict__ bias,
                                            const float* __restrict__ gamma,
                                            const float* __restrict__ beta,
                                            unsigned sbA, char* smc,
                                            int tid, int lane, int mi, int ni)
{
    float* sP   = (float*)(smc + WS_OFF);     // 6 KB param scratch in buf0
    float* sSum = (float*)(smc + RED_OFF);
    float* sSq  = sSum + 64;

    sP[tid]        = bias[tid];
    sP[512 + tid]  = gamma[tid];
    sP[1024 + tid] = beta[tid];
    if (tid < 64) { sSum[tid] = 0.f; sSq[tid] = 0.f; }
    __syncthreads();      // also: all warps done with last GEMM slice

    const int qp = lane & 3, g = lane >> 2;
    float srow[4] = {0.f, 0.f, 0.f, 0.f};
    float ssqr[4] = {0.f, 0.f, 0.f, 0.f};

#pragma unroll
    for (int mt = 0; mt < 2; mt++)
#pragma unroll
        for (int nt = 0; nt < 8; nt++)
#pragma unroll
            for (int rh = 0; rh < 2; rh++) {
                const int c0 = ni * 64 + nt * 8 + qp * 2;
                float x0 = acc[mt][nt][rh * 2]     + sP[c0];
                float x1 = acc[mt][nt][rh * 2 + 1] + sP[c0 + 1];
                acc[mt][nt][rh * 2] = x0; acc[mt][nt][rh * 2 + 1] = x1;
                const int s = mt * 2 + rh;
                srow[s] += x0 + x1;
                ssqr[s] += x0 * x0 + x1 * x1;
            }
#pragma unroll
    for (int s = 0; s < 4; s++) {
        srow[s] += __shfl_xor_sync(0xffffffffu, srow[s], 1);
        srow[s] += __shfl_xor_sync(0xffffffffu, srow[s], 2);
        ssqr[s] += __shfl_xor_sync(0xffffffffu, ssqr[s], 1);
        ssqr[s] += __shfl_xor_sync(0xffffffffu, ssqr[s], 2);
    }
    if (qp == 0) {
#pragma unroll
        for (int s = 0; s < 4; s++) {
            const int row = mi * 32 + (s >> 1) * 16 + (s & 1) * 8 + g;
            atomicAdd(&sSum[row], srow[s]);
            atomicAdd(&sSq[row],  ssqr[s]);
        }
    }
    __syncthreads();

    float mu[4], rs[4];
#pragma unroll
    for (int s = 0; s < 4; s++) {
        const int row = mi * 32 + (s >> 1) * 16 + (s & 1) * 8 + g;
        float m = sSum[row] * (1.f / 512.f);
        float v = fmaxf(sSq[row] * (1.f / 512.f) - m * m, 0.f);
        mu[s] = m; rs[s] = rsqrtf(v + EPSV);
    }
#pragma unroll
    for (int mt = 0; mt < 2; mt++)
#pragma unroll
        for (int nt = 0; nt < 8; nt++)
#pragma unroll
            for (int rh = 0; rh < 2; rh++) {
                const int s = mt * 2 + rh;
                const int c0 = ni * 64 + nt * 8 + qp * 2;
                float n0 = (acc[mt][nt][rh * 2]     - mu[s]) * rs[s] * sP[512 + c0]     + sP[1024 + c0];
                float n1 = (acc[mt][nt][rh * 2 + 1] - mu[s]) * rs[s] * sP[512 + c0 + 1] + sP[1024 + c0 + 1];
                if (ACT == 1) { n0 = fmaxf(n0, 0.f); n1 = fmaxf(n1, 0.f); }
                else if (ACT == 2) {
                    n0 = n0 / (1.f + __expf(-n0));
                    n1 = n1 / (1.f + __expf(-n1));
                }
                __half2 hp = __floats2half2_rn(n0, n1);
                const int row = mi * 32 + mt * 16 + rh * 8 + g;
                STS32(sbA + (unsigned)(row * A_STRIDE_B + c0 * 2), *(unsigned*)&hp);
            }
    __syncthreads();      // A ready + sP free before next GEMM's stage(0)
}

// ---------------------------------------------------------------------------
__global__ void __launch_bounds__(THREADS, 1)
ifs_main(const float* __restrict__ z,
         const float* __restrict__ b1, const float* __restrict__ g1,
         const float* __restrict__ be1,
         const float* __restrict__ ba, const float* __restrict__ ga,
         const float* __restrict__ bea,
         const float* __restrict__ bb, const float* __restrict__ gb,
         const float* __restrict__ beb,
         const float* __restrict__ bout,
         float* __restrict__ out, int Btot)
{
    extern __shared__ char smc[];
    const unsigned sb  = smem_u32(smc);
    const unsigned sbW = sb + WS_OFF;
    const int tid = threadIdx.x, lane = tid & 31, wid = tid >> 5;
    const int mi = wid & 1, ni = wid >> 1;            // 2M x 8N
    const int row0 = blockIdx.x * 64;

    float* sBo = (float*)(smc + BOUT_OFF);
    if (tid < 35) sBo[tid] = bout[tid];

    // z -> A (fp16)
    for (int i = tid; i < 64 * 64; i += THREADS) {
        int r = i >> 6, c4 = i & 63;
        float4 zv = *(const float4*)&z[(size_t)(row0 + r) * 256 + c4 * 4];
        __half2 h0 = __floats2half2_rn(zv.x, zv.y);
        __half2 h1 = __floats2half2_rn(zv.z, zv.w);
        STS64(sb + (unsigned)(r * A_STRIDE_B + c4 * 8),
              *(unsigned*)&h0, *(unsigned*)&h1);
    }
    __syncthreads();

    {
        float acc[2][8][4];
        gemm_full<8, 512>(g_Wt1, 256, sb, sbW, acc, tid, lane, mi, ni);
        ln_epilogue<1>(acc, b1, g1, be1, sb, smc, tid, lane, mi, ni);
    }

    // stash h (A) -> global, coalesced
    for (int c = tid; c < 64 * 64; c += THREADS) {
        int r = c >> 6, seg = c & 63;
        unsigned v0, v1, v2, v3;
        LDS128(v0, v1, v2, v3, sb + (unsigned)(r * A_STRIDE_B + seg * 16));
        uint4 vv = {v0, v1, v2, v3};
        *(uint4*)((char*)g_h + ((size_t)(row0 + r) * 512 + seg * 8) * 2) = vv;
    }
    __syncthreads();

    {
        float acc[2][8][4];
        gemm_full<8, 512>(g_Wta, 512, sb, sbW, acc, tid, lane, mi, ni);
        ln_epilogue<2>(acc, ba, ga, bea, sb, smc, tid, lane, mi, ni);
    }
    {
        float acc[2][8][4];
        gemm_full<8, 512>(g_Wtb, 512, sb, sbW, acc, tid, lane, mi, ni);
        ln_epilogue<0>(acc, bb, gb, beb, sb, smc, tid, lane, mi, ni);
    }

    // h2 = yb + h (fp32 add, single rounding)
    for (int c = tid; c < 64 * 64; c += THREADS) {
        int r = c >> 6, seg = c & 63;
        const unsigned aaddr = sb + (unsigned)(r * A_STRIDE_B + seg * 16);
        uint4 hv = *(const uint4*)((const char*)g_h +
                                   ((size_t)(row0 + r) * 512 + seg * 8) * 2);
        unsigned v0, v1, v2, v3;
        LDS128(v0, v1, v2, v3, aaddr);
        float2 a0 = __half22float2(*(__half2*)&v0), h0 = __half22float2(*(__half2*)&hv.x);
        float2 a1 = __half22float2(*(__half2*)&v1), h1 = __half22float2(*(__half2*)&hv.y);
        float2 a2 = __half22float2(*(__half2*)&v2), h2 = __half22float2(*(__half2*)&hv.z);
        float2 a3 = __half22float2(*(__half2*)&v3), h3 = __half22float2(*(__half2*)&hv.w);
        __half2 o0 = __floats2half2_rn(a0.x + h0.x, a0.y + h0.y);
        __half2 o1 = __floats2half2_rn(a1.x + h1.x, a1.y + h1.y);
        __half2 o2 = __floats2half2_rn(a2.x + h2.x, a2.y + h2.y);
        __half2 o3 = __floats2half2_rn(a3.x + h3.x, a3.y + h3.y);
        STS128(aaddr, *(unsigned*)&o0, *(unsigned*)&o1,
                      *(unsigned*)&o2, *(unsigned*)&o3);
    }
    __syncthreads();

    // ---- tail: x = h2 @ Wout(64-row pad) + bout, SVD clamp + softmax ----
    {
        float acc[2][4];
        gemm_tail(g_Wto, sb, sbW, acc, tid, lane, mi, ni);
        __syncthreads();                    // all warps done reading staging

        float* sX = (float*)(smc + WS_OFF);     // [64][65] fp32 in buf0
        const int qp = lane & 3, g = lane >> 2;
#pragma unroll
        for (int mt = 0; mt < 2; mt++)
#pragma unroll
            for (int rh = 0; rh < 2; rh++) {
                const int row = mi * 32 + mt * 16 + rh * 8 + g;
                const int col = ni * 8 + qp * 2;
                sX[row * 65 + col]     = acc[mt][rh * 2];
                sX[row * 65 + col + 1] = acc[mt][rh * 2 + 1];
            }
        __syncthreads();

        if (tid < 64) {
            const int r = tid;
            float x[35];
#pragma unroll
            for (int j = 0; j < 35; j++) x[j] = sX[r * 65 + j] + sBo[j];

            const size_t gr = (size_t)(row0 + r);
            float* op = out + gr * 30;
#pragma unroll
            for (int t = 0; t < 5; t++) {
                float a = x[t * 6], b = x[t * 6 + 1], tx = x[t * 6 + 2];
                float c = x[t * 6 + 3], d = x[t * 6 + 4], ty = x[t * 6 + 5];
                float E = 0.5f * (a + d), F = 0.5f * (a - d);
                float G = 0.5f * (c + b), H = 0.5f * (c - b);
                float Q = sqrtf(E * E + H * H);
                float R = sqrtf(F * F + G * G);
                float s1 = Q + R, s2v = Q - R;
                float s1c = fminf(s1, THRESH);
                float s2c = fminf(fmaxf(s2v, -THRESH), THRESH);
                float Qc = 0.5f * (s1c + s2c), Rc = 0.5f * (s1c - s2c);
                float rQ = Qc / fmaxf(Q, 1e-30f);
                float rR = Rc / fmaxf(R, 1e-30f);
                op[t * 6 + 0] =  rQ * E + rR * F;
                op[t * 6 + 1] = -rQ * H + rR * G;
                op[t * 6 + 2] = tx;
                op[t * 6 + 3] =  rQ * H + rR * G;
                op[t * 6 + 4] =  rQ * E - rR * F;
                op[t * 6 + 5] = ty;
            }
            float mx = x[30];
#pragma unroll
            for (int k = 1; k < 5; k++) mx = fmaxf(mx, x[30 + k]);
            float e[5], ssum = 0.f;
#pragma unroll
            for (int k = 0; k < 5; k++) { e[k] = __expf(x[30 + k] - mx); ssum += e[k]; }
            float inv = 1.f / ssum;
            float* pp = out + (size_t)Btot * 30 + gr * 5;
#pragma unroll
            for (int k = 0; k < 5; k++) pp[k] = e[k] * inv;
        }
    }
}

// ---------------------------------------------------------------------------
// single merged prep: all four WT[n][k] = fp16(W[k][n]) transposes.
__global__ void prep_all(const float* __restrict__ W1, const float* __restrict__ Wa,
                         const float* __restrict__ Wb, const float* __restrict__ Wout)
{
    int id = blockIdx.x * blockDim.x + threadIdx.x;
    if (id < 131072) {                       // W1: [256][512] -> WT1[512][256]
        int n = id >> 8, k = id & 255;
        g_Wt1[id] = __float2half_rn(W1[(size_t)k * 512 + n]);
    } else if (id < 393216) {                // Wa
        int t = id - 131072, n = t >> 9, k = t & 511;
        g_Wta[t] = __float2half_rn(Wa[(size_t)k * 512 + n]);
    } else if (id < 655360) {                // Wb
        int t = id - 393216, n = t >> 9, k = t & 511;
        g_Wtb[t] = __float2half_rn(Wb[(size_t)k * 512 + n]);
    } else if (id < 688128) {                // Wout: [512][35] -> WTo[64][512]
        int t = id - 655360, n = t >> 9, k = t & 511;
        g_Wto[t] = (n < 35) ? __float2half_rn(Wout[(size_t)k * 35 + n])
                            : __float2half_rn(0.f);
    }
}

// ---------------------------------------------------------------------------
extern "C" void kernel_launch(void* const* d_in, const int* in_sizes, int n_in,
                              void* d_out, int out_size)
{
    const float* z    = (const float*)d_in[0];
    const float* W1   = (const float*)d_in[1];
    const float* b1   = (const float*)d_in[2];
    const float* g1   = (const float*)d_in[3];
    const float* be1  = (const float*)d_in[4];
    const float* Wa   = (const float*)d_in[5];
    const float* ba   = (const float*)d_in[6];
    const float* ga   = (const float*)d_in[7];
    const float* bea  = (const float*)d_in[8];
    const float* Wb   = (const float*)d_in[9];
    const float* bb   = (const float*)d_in[10];
    const float* gb   = (const float*)d_in[11];
    const float* beb  = (const float*)d_in[12];
    const float* Wout = (const float*)d_in[13];
    const float* bout = (const float*)d_in[14];
    float* out = (float*)d_out;

    const int Btot = in_sizes[0] / 256;

    prep_all<<<(688128 + 255) / 256, 256>>>(W1, Wa, Wb, Wout);

    cudaFuncSetAttribute(ifs_main,
                         cudaFuncAttributeMaxDynamicSharedMemorySize, SMEM_BYTES);
    ifs_main<<<Btot / 64, THREADS, SMEM_BYTES>>>(
        z, b1, g1, be1, ba, ga, bea, bb, gb, beb, bout, out, Btot);
}